// round 1
// baseline (speedup 1.0000x reference)
#include <cuda_runtime.h>

#define NB 8
#define NR 16
#define NC 512
#define NS 512
#define NK 64
#define NVEC (NB*NR*NC)          /* 65536 */
#define TS 64                    /* codes per smem tile */
#define NBLK 256                 /* main-kernel blocks: 256 vectors each */

#define OFF_Z      (NVEC*NK)         /* 4194304 */
#define OFF_COMMIT (OFF_Z + NVEC)    /* 4259840 */
#define OFF_CB     (OFF_COMMIT + 1)  /* 4259841 */
#define OFF_ERR    (OFF_CB + 1)      /* 4259842 */

__device__ float g_c[NS * NK];       // codebook c = c_sum / max(count, 0.01)
__device__ float g_cnh[NS];          // 0.5 * ||c_s||^2
__device__ float g_partial[NBLK];    // per-block errs2 sums

// ---------------------------------------------------------------------------
// Kernel 1: build codebook + half-norms. One warp per code.
// ---------------------------------------------------------------------------
__global__ void __launch_bounds__(128) vq_prep(const float* __restrict__ c_sum,
                                               const float* __restrict__ c_count) {
    int warp = (blockIdx.x * blockDim.x + threadIdx.x) >> 5;
    int lane = threadIdx.x & 31;
    if (warp >= NS) return;
    float inv = 1.0f / fmaxf(c_count[warp], 0.01f);
    float a = c_sum[warp * NK + lane] * inv;
    float b = c_sum[warp * NK + 32 + lane] * inv;
    g_c[warp * NK + lane] = a;
    g_c[warp * NK + 32 + lane] = b;
    float nh = a * a + b * b;
#pragma unroll
    for (int o = 16; o; o >>= 1) nh += __shfl_xor_sync(0xffffffffu, nh, o);
    if (lane == 0) g_cnh[warp] = 0.5f * nh;
}

// ---------------------------------------------------------------------------
// Kernel 2: nearest-code search. 128 threads/block, 2 vectors/thread.
// Codebook streamed through shared memory in 64-code tiles (broadcast reads).
// ---------------------------------------------------------------------------
__global__ void __launch_bounds__(128) vq_main(const float* __restrict__ vecs,
                                               float* __restrict__ out) {
    __shared__ float sc[TS * NK];
    __shared__ float scn[TS];
    __shared__ float red[128];

    int tid = threadIdx.x;
    int n0 = blockIdx.x * 256 + tid;
    int n1 = n0 + 128;

    float v0[NK], v1[NK];
    float vn0 = 0.f, vn1 = 0.f;
    const float4* p0 = reinterpret_cast<const float4*>(vecs + (size_t)n0 * NK);
    const float4* p1 = reinterpret_cast<const float4*>(vecs + (size_t)n1 * NK);
#pragma unroll
    for (int i = 0; i < 16; i++) {
        float4 a = p0[i];
        v0[4*i+0] = a.x; v0[4*i+1] = a.y; v0[4*i+2] = a.z; v0[4*i+3] = a.w;
        vn0 += a.x*a.x + a.y*a.y + a.z*a.z + a.w*a.w;
        float4 b = p1[i];
        v1[4*i+0] = b.x; v1[4*i+1] = b.y; v1[4*i+2] = b.z; v1[4*i+3] = b.w;
        vn1 += b.x*b.x + b.y*b.y + b.z*b.z + b.w*b.w;
    }

    float best0 = -3.4e38f, best1 = -3.4e38f;
    int i0 = 0, i1 = 0;

    for (int t = 0; t < NS / TS; t++) {
        __syncthreads();  // protect previous tile from overwrite
        const float4* gc = reinterpret_cast<const float4*>(g_c + t * TS * NK);
        float4* scv = reinterpret_cast<float4*>(sc);
#pragma unroll
        for (int i = 0; i < 8; i++) scv[tid + 128 * i] = gc[tid + 128 * i];
        if (tid < TS) scn[tid] = g_cnh[t * TS + tid];
        __syncthreads();

#pragma unroll 2
        for (int s = 0; s < TS; s++) {
            float cn = scn[s];
            float a00 = -cn, a01 = 0.f, a02 = 0.f, a03 = 0.f;
            float a10 = -cn, a11 = 0.f, a12 = 0.f, a13 = 0.f;
            const float4* cp = reinterpret_cast<const float4*>(sc + s * NK);
#pragma unroll
            for (int i = 0; i < 16; i++) {
                float4 c4 = cp[i];
                a00 = fmaf(v0[4*i+0], c4.x, a00);
                a01 = fmaf(v0[4*i+1], c4.y, a01);
                a02 = fmaf(v0[4*i+2], c4.z, a02);
                a03 = fmaf(v0[4*i+3], c4.w, a03);
                a10 = fmaf(v1[4*i+0], c4.x, a10);
                a11 = fmaf(v1[4*i+1], c4.y, a11);
                a12 = fmaf(v1[4*i+2], c4.z, a12);
                a13 = fmaf(v1[4*i+3], c4.w, a13);
            }
            float d0 = (a00 + a01) + (a02 + a03);
            float d1 = (a10 + a11) + (a12 + a13);
            int sg = t * TS + s;
            if (d0 > best0) { best0 = d0; i0 = sg; }
            if (d1 > best1) { best1 = d1; i1 = sg; }
        }
    }

    float err0 = fmaxf(vn0 - 2.0f * best0, 0.0f);
    float err1 = fmaxf(vn1 - 2.0f * best1, 0.0f);

    // --- outputs ---
    // vecs_hat = c[z] gather (g_c is 128 KB, L2-hot)
    {
        float4* o0 = reinterpret_cast<float4*>(out + (size_t)n0 * NK);
        const float4* c0 = reinterpret_cast<const float4*>(g_c + (size_t)i0 * NK);
        float4* o1 = reinterpret_cast<float4*>(out + (size_t)n1 * NK);
        const float4* c1 = reinterpret_cast<const float4*>(g_c + (size_t)i1 * NK);
#pragma unroll
        for (int i = 0; i < 16; i++) { o0[i] = c0[i]; o1[i] = c1[i]; }
    }
    out[OFF_Z + n0] = (float)i0;
    out[OFF_Z + n1] = (float)i1;
    out[OFF_ERR + n0] = err0;
    out[OFF_ERR + n1] = err1;

    // deterministic block reduction of errs2
    red[tid] = err0 + err1;
    __syncthreads();
#pragma unroll
    for (int off = 64; off > 0; off >>= 1) {
        if (tid < off) red[tid] += red[tid + off];
        __syncthreads();
    }
    if (tid == 0) g_partial[blockIdx.x] = red[0];
}

// ---------------------------------------------------------------------------
// Kernel 3: finalize scalars (deterministic sequential sum).
// ---------------------------------------------------------------------------
__global__ void vq_finalize(float* __restrict__ out) {
    if (threadIdx.x == 0 && blockIdx.x == 0) {
        double d = 0.0;
        for (int i = 0; i < NBLK; i++) d += (double)g_partial[i];
        out[OFF_COMMIT] = (float)(d / (double)NVEC);
        out[OFF_CB] = 0.0f;   // l_codebook is identically 0 in forward value
    }
}

extern "C" void kernel_launch(void* const* d_in, const int* in_sizes, int n_in,
                              void* d_out, int out_size) {
    const float* vecs    = (const float*)d_in[0];
    const float* c_sum   = (const float*)d_in[1];
    const float* c_count = (const float*)d_in[2];
    float* out = (float*)d_out;

    vq_prep<<<128, 128>>>(c_sum, c_count);   // 512 warps = 512 codes
    vq_main<<<NBLK, 128>>>(vecs, out);
    vq_finalize<<<1, 32>>>(out);
}

// round 2
// speedup vs baseline: 1.1730x; 1.1730x over previous
#include <cuda_runtime.h>

#define NB 8
#define NR 16
#define NC 512
#define NS 512
#define NK 64
#define NVEC (NB*NR*NC)          /* 65536 */
#define TS 64                    /* codes per smem tile */
#define NBLK 256                 /* main-kernel blocks: 256 vectors each */

#define OFF_Z      (NVEC*NK)         /* 4194304 */
#define OFF_COMMIT (OFF_Z + NVEC)    /* 4259840 */
#define OFF_CB     (OFF_COMMIT + 1)  /* 4259841 */
#define OFF_ERR    (OFF_CB + 1)      /* 4259842 */

typedef unsigned long long u64;

__device__ float g_c[NS * NK];       // codebook c = c_sum / max(count, 0.01)
__device__ float g_cnh[NS];          // 0.5 * ||c_s||^2
__device__ float g_partial[NBLK];    // per-block errs2 sums

// ---- packed fp32x2 helpers (Blackwell FFMA2 / FADD2) ----------------------
__device__ __forceinline__ u64 fma2(u64 a, u64 b, u64 c) {
    u64 d;
    asm("fma.rn.f32x2 %0, %1, %2, %3;" : "=l"(d) : "l"(a), "l"(b), "l"(c));
    return d;
}
__device__ __forceinline__ u64 add2(u64 a, u64 b) {
    u64 d;
    asm("add.rn.f32x2 %0, %1, %2;" : "=l"(d) : "l"(a), "l"(b));
    return d;
}
__device__ __forceinline__ float hsum2(u64 a) {
    float lo, hi;
    asm("mov.b64 {%0, %1}, %2;" : "=f"(lo), "=f"(hi) : "l"(a));
    return lo + hi;
}

// ---------------------------------------------------------------------------
// Kernel 1: build codebook + half-norms. One warp per code.
// ---------------------------------------------------------------------------
__global__ void __launch_bounds__(128) vq_prep(const float* __restrict__ c_sum,
                                               const float* __restrict__ c_count) {
    int warp = (blockIdx.x * blockDim.x + threadIdx.x) >> 5;
    int lane = threadIdx.x & 31;
    if (warp >= NS) return;
    float inv = 1.0f / fmaxf(c_count[warp], 0.01f);
    float a = c_sum[warp * NK + lane] * inv;
    float b = c_sum[warp * NK + 32 + lane] * inv;
    g_c[warp * NK + lane] = a;
    g_c[warp * NK + 32 + lane] = b;
    float nh = a * a + b * b;
#pragma unroll
    for (int o = 16; o; o >>= 1) nh += __shfl_xor_sync(0xffffffffu, nh, o);
    if (lane == 0) g_cnh[warp] = 0.5f * nh;
}

// ---------------------------------------------------------------------------
// Kernel 2: nearest-code search with packed f32x2 math.
// 128 threads/block, 2 vectors/thread, codebook streamed via 16KB smem tiles.
// ---------------------------------------------------------------------------
__global__ void __launch_bounds__(128, 2) vq_main(const float* __restrict__ vecs,
                                                  float* __restrict__ out) {
    __shared__ __align__(16) float sc[TS * NK];
    __shared__ float scn[TS];
    __shared__ float red[128];

    int tid = threadIdx.x;
    int n0 = blockIdx.x * 256 + tid;
    int n1 = n0 + 128;

    // load 2 vectors into registers as packed fp32 pairs
    u64 v0[NK / 2], v1[NK / 2];
    const ulonglong2* p0 = reinterpret_cast<const ulonglong2*>(vecs + (size_t)n0 * NK);
    const ulonglong2* p1 = reinterpret_cast<const ulonglong2*>(vecs + (size_t)n1 * NK);
    u64 nv0a = 0, nv0b = 0, nv1a = 0, nv1b = 0;
#pragma unroll
    for (int i = 0; i < 16; i++) {
        ulonglong2 a = p0[i];
        v0[2 * i] = a.x;  v0[2 * i + 1] = a.y;
        nv0a = fma2(a.x, a.x, nv0a);
        nv0b = fma2(a.y, a.y, nv0b);
        ulonglong2 b = p1[i];
        v1[2 * i] = b.x;  v1[2 * i + 1] = b.y;
        nv1a = fma2(b.x, b.x, nv1a);
        nv1b = fma2(b.y, b.y, nv1b);
    }
    float vn0 = hsum2(add2(nv0a, nv0b));
    float vn1 = hsum2(add2(nv1a, nv1b));

    float best0 = -3.4e38f, best1 = -3.4e38f;
    int i0 = 0, i1 = 0;

    for (int t = 0; t < NS / TS; t++) {
        __syncthreads();  // protect previous tile from overwrite
        const float4* gc = reinterpret_cast<const float4*>(g_c + t * TS * NK);
        float4* scv = reinterpret_cast<float4*>(sc);
#pragma unroll
        for (int i = 0; i < 8; i++) scv[tid + 128 * i] = gc[tid + 128 * i];
        if (tid < TS) scn[tid] = g_cnh[t * TS + tid];
        __syncthreads();

#pragma unroll 2
        for (int s = 0; s < TS; s++) {
            float cn = scn[s];
            const ulonglong2* cp = reinterpret_cast<const ulonglong2*>(sc + s * NK);
            u64 a00 = 0, a01 = 0, a10 = 0, a11 = 0;
#pragma unroll
            for (int i = 0; i < 16; i++) {
                ulonglong2 c2 = cp[i];
                a00 = fma2(v0[2 * i],     c2.x, a00);
                a01 = fma2(v0[2 * i + 1], c2.y, a01);
                a10 = fma2(v1[2 * i],     c2.x, a10);
                a11 = fma2(v1[2 * i + 1], c2.y, a11);
            }
            float d0 = hsum2(add2(a00, a01)) - cn;
            float d1 = hsum2(add2(a10, a11)) - cn;
            int sg = t * TS + s;
            if (d0 > best0) { best0 = d0; i0 = sg; }
            if (d1 > best1) { best1 = d1; i1 = sg; }
        }
    }

    float err0 = fmaxf(vn0 - 2.0f * best0, 0.0f);
    float err1 = fmaxf(vn1 - 2.0f * best1, 0.0f);

    // --- outputs ---
    {
        float4* o0 = reinterpret_cast<float4*>(out + (size_t)n0 * NK);
        const float4* c0 = reinterpret_cast<const float4*>(g_c + (size_t)i0 * NK);
        float4* o1 = reinterpret_cast<float4*>(out + (size_t)n1 * NK);
        const float4* c1 = reinterpret_cast<const float4*>(g_c + (size_t)i1 * NK);
#pragma unroll
        for (int i = 0; i < 16; i++) { o0[i] = c0[i]; o1[i] = c1[i]; }
    }
    out[OFF_Z + n0] = (float)i0;
    out[OFF_Z + n1] = (float)i1;
    out[OFF_ERR + n0] = err0;
    out[OFF_ERR + n1] = err1;

    // deterministic block reduction of errs2
    red[tid] = err0 + err1;
    __syncthreads();
#pragma unroll
    for (int off = 64; off > 0; off >>= 1) {
        if (tid < off) red[tid] += red[tid + off];
        __syncthreads();
    }
    if (tid == 0) g_partial[blockIdx.x] = red[0];
}

// ---------------------------------------------------------------------------
// Kernel 3: finalize scalars (deterministic sequential sum).
// ---------------------------------------------------------------------------
__global__ void vq_finalize(float* __restrict__ out) {
    if (threadIdx.x == 0 && blockIdx.x == 0) {
        double d = 0.0;
        for (int i = 0; i < NBLK; i++) d += (double)g_partial[i];
        out[OFF_COMMIT] = (float)(d / (double)NVEC);
        out[OFF_CB] = 0.0f;   // l_codebook is identically 0 in forward value
    }
}

extern "C" void kernel_launch(void* const* d_in, const int* in_sizes, int n_in,
                              void* d_out, int out_size) {
    const float* vecs    = (const float*)d_in[0];
    const float* c_sum   = (const float*)d_in[1];
    const float* c_count = (const float*)d_in[2];
    float* out = (float*)d_out;

    vq_prep<<<128, 128>>>(c_sum, c_count);   // 512 warps = 512 codes
    vq_main<<<NBLK, 128>>>(vecs, out);
    vq_finalize<<<1, 32>>>(out);
}